// round 2
// baseline (speedup 1.0000x reference)
#include <cuda_runtime.h>
#include <math.h>

#define NB    4
#define NPTS  2048
#define CDIM  256
#define DFFN  1024
#define NHEAD 4
#define NKNN  16
#define MTOK  (NB*NPTS)   // 8192

// ---------------- scratch (static device globals; no allocs allowed) ----------------
__device__ __align__(16) float g_t1 [MTOK*CDIM];
__device__ __align__(16) float g_t2 [MTOK*CDIM];
__device__ __align__(16) float g_x1 [MTOK*CDIM];
__device__ __align__(16) float g_x2 [MTOK*CDIM];
__device__ __align__(16) float g_q  [MTOK*CDIM];
__device__ __align__(16) float g_k  [MTOK*CDIM];
__device__ __align__(16) float g_v  [MTOK*CDIM];
__device__ __align__(16) float g_ao [MTOK*CDIM];
__device__ __align__(16) float g_tp [MTOK*CDIM];
__device__ __align__(16) float g_y  [MTOK*CDIM];
__device__ __align__(16) float g_h  [MTOK*DFFN];
__device__ __align__(16) int   g_idx [MTOK*NKNN];
__device__ __align__(16) float g_bv  [MTOK*NKNN];

__device__ __forceinline__ float gelu_exact(float x) {
    return 0.5f * x * (1.0f + erff(x * 0.70710678118654752440f));
}

// ---------------- transpose (B,C,N) -> (B,N,C) ----------------
__global__ void transpose_kernel(const float* __restrict__ in, float* __restrict__ out) {
    __shared__ float t[32][33];
    int b  = blockIdx.z;
    int n0 = blockIdx.x * 32, c0 = blockIdx.y * 32;
    int tx = threadIdx.x, ty = threadIdx.y;            // 32 x 8
#pragma unroll
    for (int i = 0; i < 4; i++)
        t[ty + 8 * i][tx] = in[(size_t)b * CDIM * NPTS + (size_t)(c0 + ty + 8 * i) * NPTS + n0 + tx];
    __syncthreads();
#pragma unroll
    for (int i = 0; i < 4; i++)
        out[(size_t)b * NPTS * CDIM + (size_t)(n0 + ty + 8 * i) * CDIM + c0 + tx] = t[tx][ty + 8 * i];
}

// ---------------- GEMM: out[m,n] = epi( sum_k A[m,k]*W[n,k] + bias[n] ) ----------------
// MODE 0: plain    MODE 1: gelu    MODE 2: + res[m,n], store transposed (b,c,n) to d_out
template <int MODE>
__global__ void gemm_kernel(const float* __restrict__ A, const float* __restrict__ W,
                            const float* __restrict__ bias, const float* __restrict__ res,
                            float* __restrict__ out, int M, int Nout, int K) {
    __shared__ float As[16][68];
    __shared__ float Bs[16][68];
    int tid = threadIdx.x;
    int tx = tid & 15, ty = tid >> 4;
    int m0 = blockIdx.y * 64, n0 = blockIdx.x * 64;
    int lr = tid >> 2;              // 0..63
    int lk = (tid & 3) << 2;        // 0,4,8,12
    float acc[4][4] = {};
    for (int k0 = 0; k0 < K; k0 += 16) {
        float4 a4 = *reinterpret_cast<const float4*>(A + (size_t)(m0 + lr) * K + k0 + lk);
        float4 b4 = *reinterpret_cast<const float4*>(W + (size_t)(n0 + lr) * K + k0 + lk);
        As[lk + 0][lr] = a4.x; As[lk + 1][lr] = a4.y; As[lk + 2][lr] = a4.z; As[lk + 3][lr] = a4.w;
        Bs[lk + 0][lr] = b4.x; Bs[lk + 1][lr] = b4.y; Bs[lk + 2][lr] = b4.z; Bs[lk + 3][lr] = b4.w;
        __syncthreads();
#pragma unroll
        for (int kk = 0; kk < 16; kk++) {
            float ar[4], br[4];
#pragma unroll
            for (int i = 0; i < 4; i++) ar[i] = As[kk][ty * 4 + i];
#pragma unroll
            for (int j = 0; j < 4; j++) br[j] = Bs[kk][tx * 4 + j];
#pragma unroll
            for (int i = 0; i < 4; i++)
#pragma unroll
                for (int j = 0; j < 4; j++)
                    acc[i][j] = fmaf(ar[i], br[j], acc[i][j]);
        }
        __syncthreads();
    }
#pragma unroll
    for (int i = 0; i < 4; i++) {
        int m = m0 + ty * 4 + i;
#pragma unroll
        for (int j = 0; j < 4; j++) {
            int n = n0 + tx * 4 + j;
            float v = acc[i][j] + bias[n];
            if (MODE == 1) v = gelu_exact(v);
            if (MODE == 2) {
                v += res[(size_t)m * CDIM + n];
                int b = m >> 11, nn = m & (NPTS - 1);
                out[((size_t)b * CDIM + n) * NPTS + nn] = v;
            } else {
                out[(size_t)m * Nout + n] = v;
            }
        }
    }
}

// ---------------- LayerNorm (optionally x += res first), row = 256 ----------------
__global__ void ln_kernel(const float* __restrict__ x, const float* __restrict__ res,
                          const float* __restrict__ g, const float* __restrict__ be,
                          float* __restrict__ out) {
    __shared__ float sb[256];
    int m = blockIdx.x, c = threadIdx.x;
    float v = x[(size_t)m * CDIM + c];
    if (res) v += res[(size_t)m * CDIM + c];
    sb[c] = v; __syncthreads();
    for (int o = 128; o > 0; o >>= 1) { if (c < o) sb[c] += sb[c + o]; __syncthreads(); }
    float mean = sb[0] * (1.0f / 256.0f);
    __syncthreads();
    float d = v - mean;
    sb[c] = d * d; __syncthreads();
    for (int o = 128; o > 0; o >>= 1) { if (c < o) sb[c] += sb[c + o]; __syncthreads(); }
    float var = sb[0] * (1.0f / 256.0f);
    out[(size_t)m * CDIM + c] = d * rsqrtf(var + 1e-5f) * g[c] + be[c];
}

// ---------------- KNN top-16 + rel-pos bias MLP ----------------
// one block per (b, query i); pos layout (B,3,N)
__global__ void knn_kernel(const float* __restrict__ pos,
                           const float* __restrict__ Wr1, const float* __restrict__ br1,
                           const float* __restrict__ Wr2, const float* __restrict__ br2,
                           int* __restrict__ idx_out, float* __restrict__ bias_out) {
    __shared__ float dist[NPTS];
    __shared__ unsigned long long rbuf[256];
    __shared__ int selj[NKNN];
    int bq = blockIdx.x;
    int b = bq >> 11, i = bq & (NPTS - 1);
    int t = threadIdx.x;
    const float* P = pos + (size_t)b * 3 * NPTS;
    float xi = P[i], yi = P[NPTS + i], zi = P[2 * NPTS + i];
    float sqi = xi * xi + yi * yi + zi * zi;
    for (int j = t; j < NPTS; j += 256) {
        float xj = P[j], yj = P[NPTS + j], zj = P[2 * NPTS + j];
        float sqj = xj * xj + yj * yj + zj * zj;
        float dot = xi * xj + yi * yj + zi * zj;
        dist[j] = sqi + sqj - 2.0f * dot;
    }
    __syncthreads();
    for (int s = 0; s < NKNN; s++) {
        unsigned long long best = ~0ull;
        for (int j = t; j < NPTS; j += 256) {
            unsigned int db = __float_as_uint(dist[j]);
            db = (db & 0x80000000u) ? ~db : (db | 0x80000000u);  // total order incl. negatives
            unsigned long long key = ((unsigned long long)db << 32) | (unsigned int)j;
            if (key < best) best = key;
        }
        rbuf[t] = best; __syncthreads();
        for (int o = 128; o > 0; o >>= 1) {
            if (t < o && rbuf[t + o] < rbuf[t]) rbuf[t] = rbuf[t + o];
            __syncthreads();
        }
        if (t == 0) {
            int j = (int)(rbuf[0] & 0xffffffffull);
            selj[s] = j;
            dist[j] = __int_as_float(0x7f800000);  // +inf, exclude
        }
        __syncthreads();
    }
    if (t < NKNN) {
        int j = selj[t];
        float rx = xi - P[j], ry = yi - P[NPTS + j], rz = zi - P[2 * NPTS + j];
        float acc = 0.0f;
#pragma unroll 8
        for (int o = 0; o < 64; o++) {
            float hp = Wr1[o * 3] * rx + Wr1[o * 3 + 1] * ry + Wr1[o * 3 + 2] * rz + br1[o];
            acc += Wr2[o] * gelu_exact(hp);
        }
        idx_out[(size_t)bq * NKNN + t] = j;
        bias_out[(size_t)bq * NKNN + t] = acc + br2[0];
    }
}

// ---------------- sparse attention: block per token, warp per head ----------------
__global__ void attn_kernel(const float* __restrict__ q, const float* __restrict__ k,
                            const float* __restrict__ v, const int* __restrict__ idx,
                            const float* __restrict__ bias, float* __restrict__ out) {
    __shared__ int   sj[NKNN];
    __shared__ float sb[NKNN];
    __shared__ float sc[NHEAD][NKNN];
    int m = blockIdx.x;
    int b = m >> 11;
    int warp = threadIdx.x >> 5, lane = threadIdx.x & 31;
    if (threadIdx.x < NKNN) {
        sj[threadIdx.x] = idx[(size_t)m * NKNN + threadIdx.x];
        sb[threadIdx.x] = bias[(size_t)m * NKNN + threadIdx.x];
    }
    __syncthreads();
    int hoff = warp * 64;
    float q0 = q[(size_t)m * CDIM + hoff + lane];
    float q1 = q[(size_t)m * CDIM + hoff + 32 + lane];
    for (int kk = 0; kk < NKNN; kk++) {
        int j = sj[kk];
        size_t base = ((size_t)b * NPTS + j) * CDIM + hoff;
        float d = q0 * k[base + lane] + q1 * k[base + 32 + lane];
#pragma unroll
        for (int o = 16; o > 0; o >>= 1) d += __shfl_xor_sync(0xffffffffu, d, o);
        if (lane == 0) sc[warp][kk] = d * 0.125f + sb[kk];
    }
    __syncwarp();
    float mx = -3.4e38f;
#pragma unroll
    for (int kk = 0; kk < NKNN; kk++) mx = fmaxf(mx, sc[warp][kk]);
    float w[NKNN]; float sum = 0.0f;
#pragma unroll
    for (int kk = 0; kk < NKNN; kk++) { w[kk] = expf(sc[warp][kk] - mx); sum += w[kk]; }
    float inv = 1.0f / sum;
    float o0 = 0.0f, o1 = 0.0f;
    for (int kk = 0; kk < NKNN; kk++) {
        int j = sj[kk];
        size_t base = ((size_t)b * NPTS + j) * CDIM + hoff;
        float ww = w[kk] * inv;
        o0 += ww * v[base + lane];
        o1 += ww * v[base + 32 + lane];
    }
    out[(size_t)m * CDIM + hoff + lane]      = o0;
    out[(size_t)m * CDIM + hoff + 32 + lane] = o1;
}

// ---------------- driver ----------------
extern "C" void kernel_launch(void* const* d_in, const int* in_sizes, int n_in,
                              void* d_out, int out_size) {
    const float* src1 = (const float*)d_in[0];
    const float* src2 = (const float*)d_in[1];
    const float* pos  = (const float*)d_in[2];
    const float* Wp   = (const float*)d_in[3];
    const float* bp   = (const float*)d_in[4];
    const float* Wr1  = (const float*)d_in[5];
    const float* br1  = (const float*)d_in[6];
    const float* Wr2  = (const float*)d_in[7];
    const float* br2  = (const float*)d_in[8];
    const float* Wqkv = (const float*)d_in[9];
    const float* bqkv = (const float*)d_in[10];
    const float* Wo   = (const float*)d_in[11];
    const float* bo   = (const float*)d_in[12];
    const float* g13  = (const float*)d_in[13];
    const float* b13  = (const float*)d_in[14];
    const float* g12  = (const float*)d_in[15];
    const float* b12  = (const float*)d_in[16];
    const float* W1   = (const float*)d_in[17];
    const float* b1   = (const float*)d_in[18];
    const float* W2   = (const float*)d_in[19];
    const float* b2   = (const float*)d_in[20];
    float* out = (float*)d_out;

    float *t1, *t2, *x1, *x2, *qb, *kb, *vb, *ao, *tp, *y, *h, *bv;
    int* idxb;
    cudaGetSymbolAddress((void**)&t1, g_t1);
    cudaGetSymbolAddress((void**)&t2, g_t2);
    cudaGetSymbolAddress((void**)&x1, g_x1);
    cudaGetSymbolAddress((void**)&x2, g_x2);
    cudaGetSymbolAddress((void**)&qb, g_q);
    cudaGetSymbolAddress((void**)&kb, g_k);
    cudaGetSymbolAddress((void**)&vb, g_v);
    cudaGetSymbolAddress((void**)&ao, g_ao);
    cudaGetSymbolAddress((void**)&tp, g_tp);
    cudaGetSymbolAddress((void**)&y,  g_y);
    cudaGetSymbolAddress((void**)&h,  g_h);
    cudaGetSymbolAddress((void**)&bv, g_bv);
    cudaGetSymbolAddress((void**)&idxb, g_idx);

    dim3 gT(NPTS / 32, CDIM / 32, NB), bT(32, 8);
    transpose_kernel<<<gT, bT>>>(src1, t1);
    transpose_kernel<<<gT, bT>>>(src2, t2);

    dim3 gP(CDIM / 64, MTOK / 64);
    gemm_kernel<0><<<gP, 256>>>(t1, Wp, bp, nullptr, x1, MTOK, CDIM, CDIM);
    gemm_kernel<0><<<gP, 256>>>(t2, Wp, bp, nullptr, x2, MTOK, CDIM, CDIM);

    ln_kernel<<<MTOK, 256>>>(x1, nullptr, g13, b13, x1);
    ln_kernel<<<MTOK, 256>>>(x2, nullptr, g13, b13, x2);

    knn_kernel<<<MTOK, 256>>>(pos, Wr1, br1, Wr2, br2, idxb, bv);

    gemm_kernel<0><<<gP, 256>>>(x1, Wqkv,                bqkv,       nullptr, qb, MTOK, CDIM, CDIM);
    gemm_kernel<0><<<gP, 256>>>(x2, Wqkv + CDIM * CDIM,  bqkv + CDIM,     nullptr, kb, MTOK, CDIM, CDIM);
    gemm_kernel<0><<<gP, 256>>>(x2, Wqkv + 2 * CDIM * CDIM, bqkv + 2 * CDIM, nullptr, vb, MTOK, CDIM, CDIM);

    attn_kernel<<<MTOK, 128>>>(qb, kb, vb, idxb, bv, ao);

    gemm_kernel<0><<<gP, 256>>>(ao, Wo, bo, nullptr, tp, MTOK, CDIM, CDIM);

    ln_kernel<<<MTOK, 256>>>(x1, tp, g12, b12, y);

    dim3 gF1(DFFN / 64, MTOK / 64);
    gemm_kernel<1><<<gF1, 256>>>(y, W1, b1, nullptr, h, MTOK, DFFN, CDIM);
    gemm_kernel<2><<<gP, 256>>>(h, W2, b2, y, out, MTOK, CDIM, DFFN);
}

// round 4
// speedup vs baseline: 1.3116x; 1.3116x over previous
#include <cuda_runtime.h>
#include <math.h>

#define NB    4
#define NPTS  2048
#define CDIM  256
#define DFFN  1024
#define NHEAD 4
#define NKNN  16
#define MTOK  (NB*NPTS)   // 8192

// ---------------- scratch (static device globals; no allocs allowed) ----------------
__device__ __align__(16) float g_t1 [MTOK*CDIM];
__device__ __align__(16) float g_t2 [MTOK*CDIM];
__device__ __align__(16) float g_x1 [MTOK*CDIM];
__device__ __align__(16) float g_x2 [MTOK*CDIM];
__device__ __align__(16) float g_q  [MTOK*CDIM];
__device__ __align__(16) float g_k  [MTOK*CDIM];
__device__ __align__(16) float g_v  [MTOK*CDIM];
__device__ __align__(16) float g_ao [MTOK*CDIM];
__device__ __align__(16) float g_tp [MTOK*CDIM];
__device__ __align__(16) float g_y  [MTOK*CDIM];
__device__ __align__(16) float g_h  [MTOK*DFFN];
__device__ __align__(16) int   g_idx [MTOK*NKNN];
__device__ __align__(16) float g_bv  [MTOK*NKNN];

__device__ __forceinline__ float gelu_exact(float x) {
    return 0.5f * x * (1.0f + erff(x * 0.70710678118654752440f));
}

__device__ __forceinline__ unsigned tf32_of(float x) {
    unsigned u; asm("cvt.rna.tf32.f32 %0, %1;" : "=r"(u) : "f"(x)); return u;
}

#define CP_ASYNC16(smem_u32, gptr) \
    asm volatile("cp.async.cg.shared.global [%0], [%1], 16;" :: "r"(smem_u32), "l"(gptr))

// ---------------- transpose (B,C,N) -> (B,N,C) ----------------
__global__ void transpose_kernel(const float* __restrict__ in, float* __restrict__ out) {
    __shared__ float t[32][33];
    int b  = blockIdx.z;
    int n0 = blockIdx.x * 32, c0 = blockIdx.y * 32;
    int tx = threadIdx.x, ty = threadIdx.y;            // 32 x 8
#pragma unroll
    for (int i = 0; i < 4; i++)
        t[ty + 8 * i][tx] = in[(size_t)b * CDIM * NPTS + (size_t)(c0 + ty + 8 * i) * NPTS + n0 + tx];
    __syncthreads();
#pragma unroll
    for (int i = 0; i < 4; i++)
        out[(size_t)b * NPTS * CDIM + (size_t)(n0 + ty + 8 * i) * CDIM + c0 + tx] = t[tx][ty + 8 * i];
}

// ---------------- tensor-core GEMM (3xTF32): out[m,n] = epi(sum_k A[m,k]*W[n,k] + bias[n]) ----
// CTA tile 128x128x16, 8 warps (2m x 4n), warp tile 64x32, mma.m16n8k8.tf32 x3 passes.
// MODE 0: plain   MODE 1: gelu   MODE 2: + res[m,n], store transposed (b,c,n)
#define SROW 20   // padded smem row stride (floats); conflict-free for frag patterns

template <int MODE>
__global__ void __launch_bounds__(256) mma_gemm(
        const float* __restrict__ A, const float* __restrict__ W,
        const float* __restrict__ bias, const float* __restrict__ res,
        float* __restrict__ out, int M, int N, int K) {
    __shared__ float As[2][128 * SROW];
    __shared__ float Bs[2][128 * SROW];
    const int tid = threadIdx.x;
    const int lane = tid & 31, warp = tid >> 5;
    const int g = lane >> 2, tig = lane & 3;
    const int wm = (warp & 1) * 64, wn = (warp >> 1) * 32;
    const int m0 = blockIdx.y * 128, n0 = blockIdx.x * 128;

    const int lrow = tid >> 2;            // 0..63
    const int lcol = (tid & 3) * 4;       // 0,4,8,12
    const float* Ag = A + (size_t)(m0 + lrow) * K + lcol;
    const float* Wg = W + (size_t)(n0 + lrow) * K + lcol;
    const unsigned sA = (unsigned)__cvta_generic_to_shared(&As[0][0]);
    const unsigned sB = (unsigned)__cvta_generic_to_shared(&Bs[0][0]);
    const unsigned bufB = 128 * SROW * 4;
    const unsigned dstOff = (unsigned)(lrow * SROW + lcol) * 4;

    float c[4][4][4];
#pragma unroll
    for (int i = 0; i < 4; i++)
#pragma unroll
        for (int j = 0; j < 4; j++)
#pragma unroll
            for (int r = 0; r < 4; r++) c[i][j][r] = 0.0f;

    const int nIter = K / 16;
    // prologue: prefetch tile 0
    {
        CP_ASYNC16(sA + dstOff, Ag);
        CP_ASYNC16(sA + dstOff + 64 * SROW * 4, Ag + (size_t)64 * K);
        CP_ASYNC16(sB + dstOff, Wg);
        CP_ASYNC16(sB + dstOff + 64 * SROW * 4, Wg + (size_t)64 * K);
        asm volatile("cp.async.commit_group;");
    }

    for (int kt = 0; kt < nIter; kt++) {
        asm volatile("cp.async.wait_group 0;");
        __syncthreads();
        const int buf = kt & 1;
        if (kt + 1 < nIter) {
            const int k1 = (kt + 1) * 16;
            const unsigned d = (buf ^ 1) * bufB + dstOff;
            CP_ASYNC16(sA + d, Ag + k1);
            CP_ASYNC16(sA + d + 64 * SROW * 4, Ag + (size_t)64 * K + k1);
            CP_ASYNC16(sB + d, Wg + k1);
            CP_ASYNC16(sB + d + 64 * SROW * 4, Wg + (size_t)64 * K + k1);
            asm volatile("cp.async.commit_group;");
        }
        const float* as = &As[buf][0];
        const float* bs = &Bs[buf][0];
#pragma unroll
        for (int ks = 0; ks < 2; ks++) {
            unsigned ah[4][4], al[4][4], bh[4][2], bl[4][2];
#pragma unroll
            for (int mt = 0; mt < 4; mt++) {
                const float* p = as + (wm + mt * 16 + g) * SROW + ks * 8 + tig;
                float a0 = p[0], a1 = p[8 * SROW], a2 = p[4], a3 = p[8 * SROW + 4];
                ah[mt][0] = tf32_of(a0); al[mt][0] = tf32_of(a0 - __uint_as_float(ah[mt][0]));
                ah[mt][1] = tf32_of(a1); al[mt][1] = tf32_of(a1 - __uint_as_float(ah[mt][1]));
                ah[mt][2] = tf32_of(a2); al[mt][2] = tf32_of(a2 - __uint_as_float(ah[mt][2]));
                ah[mt][3] = tf32_of(a3); al[mt][3] = tf32_of(a3 - __uint_as_float(ah[mt][3]));
            }
#pragma unroll
            for (int nt = 0; nt < 4; nt++) {
                const float* p = bs + (wn + nt * 8 + g) * SROW + ks * 8 + tig;
                float b0 = p[0], b1 = p[4];
                bh[nt][0] = tf32_of(b0); bl[nt][0] = tf32_of(b0 - __uint_as_float(bh[nt][0]));
                bh[nt][1] = tf32_of(b1); bl[nt][1] = tf32_of(b1 - __uint_as_float(bh[nt][1]));
            }
#pragma unroll
            for (int mt = 0; mt < 4; mt++)
#pragma unroll
                for (int nt = 0; nt < 4; nt++) {
                    float* cc = c[mt][nt];
#define MMA_TF32(A0,A1,A2,A3,B0,B1) \
    asm volatile("mma.sync.aligned.m16n8k8.row.col.f32.tf32.tf32.f32 " \
        "{%0,%1,%2,%3}, {%4,%5,%6,%7}, {%8,%9}, {%0,%1,%2,%3};" \
        : "+f"(cc[0]), "+f"(cc[1]), "+f"(cc[2]), "+f"(cc[3]) \
        : "r"(A0), "r"(A1), "r"(A2), "r"(A3), "r"(B0), "r"(B1))
                    MMA_TF32(al[mt][0], al[mt][1], al[mt][2], al[mt][3], bh[nt][0], bh[nt][1]);
                    MMA_TF32(ah[mt][0], ah[mt][1], ah[mt][2], ah[mt][3], bl[nt][0], bl[nt][1]);
                    MMA_TF32(ah[mt][0], ah[mt][1], ah[mt][2], ah[mt][3], bh[nt][0], bh[nt][1]);
#undef MMA_TF32
                }
        }
        __syncthreads();
    }

    // epilogue
#pragma unroll
    for (int mt = 0; mt < 4; mt++)
#pragma unroll
        for (int nt = 0; nt < 4; nt++) {
            int row = m0 + wm + mt * 16 + g;
            int col = n0 + wn + nt * 8 + tig * 2;
#pragma unroll
            for (int half = 0; half < 2; half++) {
                int m = row + half * 8;
                float v0 = c[mt][nt][half * 2 + 0] + bias[col];
                float v1 = c[mt][nt][half * 2 + 1] + bias[col + 1];
                if (MODE == 1) { v0 = gelu_exact(v0); v1 = gelu_exact(v1); }
                if (MODE == 2) {
                    v0 += res[(size_t)m * CDIM + col];
                    v1 += res[(size_t)m * CDIM + col + 1];
                    int b = m >> 11, nn = m & (NPTS - 1);
                    out[((size_t)b * CDIM + col) * NPTS + nn]     = v0;
                    out[((size_t)b * CDIM + col + 1) * NPTS + nn] = v1;
                } else {
                    float2 v2 = make_float2(v0, v1);
                    *reinterpret_cast<float2*>(out + (size_t)m * N + col) = v2;
                }
            }
        }
}

// ---------------- LayerNorm (optionally x += res first), row = 256 ----------------
__global__ void ln_kernel(const float* __restrict__ x, const float* __restrict__ res,
                          const float* __restrict__ g, const float* __restrict__ be,
                          float* __restrict__ out) {
    __shared__ float sb[256];
    int m = blockIdx.x, c = threadIdx.x;
    float v = x[(size_t)m * CDIM + c];
    if (res) v += res[(size_t)m * CDIM + c];
    sb[c] = v; __syncthreads();
    for (int o = 128; o > 0; o >>= 1) { if (c < o) sb[c] += sb[c + o]; __syncthreads(); }
    float mean = sb[0] * (1.0f / 256.0f);
    __syncthreads();
    float d = v - mean;
    sb[c] = d * d; __syncthreads();
    for (int o = 128; o > 0; o >>= 1) { if (c < o) sb[c] += sb[c + o]; __syncthreads(); }
    float var = sb[0] * (1.0f / 256.0f);
    out[(size_t)m * CDIM + c] = d * rsqrtf(var + 1e-5f) * g[c] + be[c];
}

// ---------------- KNN top-16 + rel-pos bias MLP ----------------
__global__ void knn_kernel(const float* __restrict__ pos,
                           const float* __restrict__ Wr1, const float* __restrict__ br1,
                           const float* __restrict__ Wr2, const float* __restrict__ br2,
                           int* __restrict__ idx_out, float* __restrict__ bias_out) {
    __shared__ float dist[NPTS];
    __shared__ unsigned long long rbuf[256];
    __shared__ int selj[NKNN];
    int bq = blockIdx.x;
    int b = bq >> 11, i = bq & (NPTS - 1);
    int t = threadIdx.x;
    const float* P = pos + (size_t)b * 3 * NPTS;
    float xi = P[i], yi = P[NPTS + i], zi = P[2 * NPTS + i];
    float sqi = xi * xi + yi * yi + zi * zi;
    for (int j = t; j < NPTS; j += 256) {
        float xj = P[j], yj = P[NPTS + j], zj = P[2 * NPTS + j];
        float sqj = xj * xj + yj * yj + zj * zj;
        float dot = xi * xj + yi * yj + zi * zj;
        dist[j] = sqi + sqj - 2.0f * dot;
    }
    __syncthreads();
    for (int s = 0; s < NKNN; s++) {
        unsigned long long best = ~0ull;
        for (int j = t; j < NPTS; j += 256) {
            unsigned int db = __float_as_uint(dist[j]);
            db = (db & 0x80000000u) ? ~db : (db | 0x80000000u);
            unsigned long long key = ((unsigned long long)db << 32) | (unsigned int)j;
            if (key < best) best = key;
        }
        rbuf[t] = best; __syncthreads();
        for (int o = 128; o > 0; o >>= 1) {
            if (t < o && rbuf[t + o] < rbuf[t]) rbuf[t] = rbuf[t + o];
            __syncthreads();
        }
        if (t == 0) {
            int j = (int)(rbuf[0] & 0xffffffffull);
            selj[s] = j;
            dist[j] = __int_as_float(0x7f800000);
        }
        __syncthreads();
    }
    if (t < NKNN) {
        int j = selj[t];
        float rx = xi - P[j], ry = yi - P[NPTS + j], rz = zi - P[2 * NPTS + j];
        float acc = 0.0f;
#pragma unroll 8
        for (int o = 0; o < 64; o++) {
            float hp = Wr1[o * 3] * rx + Wr1[o * 3 + 1] * ry + Wr1[o * 3 + 2] * rz + br1[o];
            acc += Wr2[o] * gelu_exact(hp);
        }
        idx_out[(size_t)bq * NKNN + t] = j;
        bias_out[(size_t)bq * NKNN + t] = acc + br2[0];
    }
}

// ---------------- sparse attention: block per token, warp per head ----------------
__global__ void attn_kernel(const float* __restrict__ q, const float* __restrict__ k,
                            const float* __restrict__ v, const int* __restrict__ idx,
                            const float* __restrict__ bias, float* __restrict__ out) {
    __shared__ int   sj[NKNN];
    __shared__ float sb[NKNN];
    __shared__ float sc[NHEAD][NKNN];
    int m = blockIdx.x;
    int b = m >> 11;
    int warp = threadIdx.x >> 5, lane = threadIdx.x & 31;
    if (threadIdx.x < NKNN) {
        sj[threadIdx.x] = idx[(size_t)m * NKNN + threadIdx.x];
        sb[threadIdx.x] = bias[(size_t)m * NKNN + threadIdx.x];
    }
    __syncthreads();
    int hoff = warp * 64;
    float q0 = q[(size_t)m * CDIM + hoff + lane];
    float q1 = q[(size_t)m * CDIM + hoff + 32 + lane];
    for (int kk = 0; kk < NKNN; kk++) {
        int j = sj[kk];
        size_t base = ((size_t)b * NPTS + j) * CDIM + hoff;
        float d = q0 * k[base + lane] + q1 * k[base + 32 + lane];
#pragma unroll
        for (int o = 16; o > 0; o >>= 1) d += __shfl_xor_sync(0xffffffffu, d, o);
        if (lane == 0) sc[warp][kk] = d * 0.125f + sb[kk];
    }
    __syncwarp();
    float mx = -3.4e38f;
#pragma unroll
    for (int kk = 0; kk < NKNN; kk++) mx = fmaxf(mx, sc[warp][kk]);
    float w[NKNN]; float sum = 0.0f;
#pragma unroll
    for (int kk = 0; kk < NKNN; kk++) { w[kk] = expf(sc[warp][kk] - mx); sum += w[kk]; }
    float inv = 1.0f / sum;
    float o0 = 0.0f, o1 = 0.0f;
    for (int kk = 0; kk < NKNN; kk++) {
        int j = sj[kk];
        size_t base = ((size_t)b * NPTS + j) * CDIM + hoff;
        float ww = w[kk] * inv;
        o0 += ww * v[base + lane];
        o1 += ww * v[base + 32 + lane];
    }
    out[(size_t)m * CDIM + hoff + lane]      = o0;
    out[(size_t)m * CDIM + hoff + 32 + lane] = o1;
}

// ---------------- driver ----------------
extern "C" void kernel_launch(void* const* d_in, const int* in_sizes, int n_in,
                              void* d_out, int out_size) {
    const float* src1 = (const float*)d_in[0];
    const float* src2 = (const float*)d_in[1];
    const float* pos  = (const float*)d_in[2];
    const float* Wp   = (const float*)d_in[3];
    const float* bp   = (const float*)d_in[4];
    const float* Wr1  = (const float*)d_in[5];
    const float* br1  = (const float*)d_in[6];
    const float* Wr2  = (const float*)d_in[7];
    const float* br2  = (const float*)d_in[8];
    const float* Wqkv = (const float*)d_in[9];
    const float* bqkv = (const float*)d_in[10];
    const float* Wo   = (const float*)d_in[11];
    const float* bo   = (const float*)d_in[12];
    const float* g13  = (const float*)d_in[13];
    const float* b13  = (const float*)d_in[14];
    const float* g12  = (const float*)d_in[15];
    const float* b12  = (const float*)d_in[16];
    const float* W1   = (const float*)d_in[17];
    const float* b1   = (const float*)d_in[18];
    const float* W2   = (const float*)d_in[19];
    const float* b2   = (const float*)d_in[20];
    float* out = (float*)d_out;

    float *t1, *t2, *x1, *x2, *qb, *kb, *vb, *ao, *tp, *y, *h, *bv;
    int* idxb;
    cudaGetSymbolAddress((void**)&t1, g_t1);
    cudaGetSymbolAddress((void**)&t2, g_t2);
    cudaGetSymbolAddress((void**)&x1, g_x1);
    cudaGetSymbolAddress((void**)&x2, g_x2);
    cudaGetSymbolAddress((void**)&qb, g_q);
    cudaGetSymbolAddress((void**)&kb, g_k);
    cudaGetSymbolAddress((void**)&vb, g_v);
    cudaGetSymbolAddress((void**)&ao, g_ao);
    cudaGetSymbolAddress((void**)&tp, g_tp);
    cudaGetSymbolAddress((void**)&y,  g_y);
    cudaGetSymbolAddress((void**)&h,  g_h);
    cudaGetSymbolAddress((void**)&bv, g_bv);
    cudaGetSymbolAddress((void**)&idxb, g_idx);

    dim3 gT(NPTS / 32, CDIM / 32, NB), bT(32, 8);
    transpose_kernel<<<gT, bT>>>(src1, t1);
    transpose_kernel<<<gT, bT>>>(src2, t2);

    dim3 gP(CDIM / 128, MTOK / 128);
    mma_gemm<0><<<gP, 256>>>(t1, Wp, bp, nullptr, x1, MTOK, CDIM, CDIM);
    mma_gemm<0><<<gP, 256>>>(t2, Wp, bp, nullptr, x2, MTOK, CDIM, CDIM);

    ln_kernel<<<MTOK, 256>>>(x1, nullptr, g13, b13, x1);
    ln_kernel<<<MTOK, 256>>>(x2, nullptr, g13, b13, x2);

    knn_kernel<<<MTOK, 256>>>(pos, Wr1, br1, Wr2, br2, idxb, bv);

    mma_gemm<0><<<gP, 256>>>(x1, Wqkv,                   bqkv,            nullptr, qb, MTOK, CDIM, CDIM);
    mma_gemm<0><<<gP, 256>>>(x2, Wqkv + CDIM * CDIM,     bqkv + CDIM,     nullptr, kb, MTOK, CDIM, CDIM);
    mma_gemm<0><<<gP, 256>>>(x2, Wqkv + 2 * CDIM * CDIM, bqkv + 2 * CDIM, nullptr, vb, MTOK, CDIM, CDIM);

    attn_kernel<<<MTOK, 128>>>(qb, kb, vb, idxb, bv, ao);

    mma_gemm<0><<<gP, 256>>>(ao, Wo, bo, nullptr, tp, MTOK, CDIM, CDIM);

    ln_kernel<<<MTOK, 256>>>(x1, tp, g12, b12, y);

    dim3 gF1(DFFN / 128, MTOK / 128);
    mma_gemm<1><<<gF1, 256>>>(y, W1, b1, nullptr, h, MTOK, DFFN, CDIM);
    mma_gemm<2><<<gP, 256>>>(h, W2, b2, y, out, MTOK, CDIM, DFFN);
}

// round 6
// speedup vs baseline: 1.6395x; 1.2500x over previous
#include <cuda_runtime.h>
#include <cuda_bf16.h>
#include <math.h>

#define NB    4
#define NPTS  2048
#define CDIM  256
#define DFFN  1024
#define NHEAD 4
#define NKNN  16
#define MTOK  (NB*NPTS)   // 8192

// weight-split segment offsets (elements)
#define W_P    0
#define W_QKV  65536
#define W_O    262144
#define W_1    327680
#define W_2    589824
#define W_TOT  851968

// ---------------- scratch ----------------
__device__ __align__(16) float g_t [2*MTOK*CDIM];
__device__ __align__(16) float g_x [2*MTOK*CDIM];
__device__ __align__(16) float g_q [MTOK*CDIM];
__device__ __align__(16) float g_kv[MTOK*512];
__device__ __align__(16) float g_ao[MTOK*CDIM];
__device__ __align__(16) float g_tp[MTOK*CDIM];
__device__ __align__(16) float g_y [MTOK*CDIM];
__device__ __align__(16) float g_h [MTOK*DFFN];
__device__ __align__(16) unsigned short g_wh[W_TOT];
__device__ __align__(16) unsigned short g_wl[W_TOT];
__device__ __align__(16) int   g_idx[MTOK*NKNN];
__device__ __align__(16) float g_bv [MTOK*NKNN];

__device__ __forceinline__ float gelu_exact(float x) {
    return 0.5f * x * (1.0f + erff(x * 0.70710678118654752440f));
}

#define CP_ASYNC16(smem_u32, gptr) \
    asm volatile("cp.async.cg.shared.global [%0], [%1], 16;" :: "r"(smem_u32), "l"(gptr))

// split a float pair (x0 = even-k, x1 = odd-k) into packed bf16 hi and lo
__device__ __forceinline__ void split_pair(float x0, float x1, unsigned& hi, unsigned& lo) {
    unsigned r0 = __float_as_uint(x0), r1 = __float_as_uint(x1);
    asm("prmt.b32 %0, %1, %2, 0x7632;" : "=r"(hi) : "r"(r0), "r"(r1));
    float l0 = x0 - __uint_as_float(r0 & 0xffff0000u);
    float l1 = x1 - __uint_as_float(r1 & 0xffff0000u);
    asm("cvt.rn.bf16x2.f32 %0, %1, %2;" : "=r"(lo) : "f"(l1), "f"(l0));
}

// ---------------- weight split prep ----------------
__global__ void split_weights(const float* __restrict__ Wp, const float* __restrict__ Wqkv,
                              const float* __restrict__ Wo, const float* __restrict__ W1,
                              const float* __restrict__ W2,
                              unsigned short* __restrict__ wh, unsigned short* __restrict__ wl) {
    int i = blockIdx.x * 256 + threadIdx.x;
    if (i >= W_TOT) return;
    const float* src; int off;
    if      (i < W_QKV) { src = Wp;   off = i; }
    else if (i < W_O)   { src = Wqkv; off = i - W_QKV; }
    else if (i < W_1)   { src = Wo;   off = i - W_O; }
    else if (i < W_2)   { src = W1;   off = i - W_1; }
    else                { src = W2;   off = i - W_2; }
    float x = src[off];
    unsigned r = __float_as_uint(x);
    wh[i] = (unsigned short)(r >> 16);
    float lo = x - __uint_as_float(r & 0xffff0000u);
    __nv_bfloat16 lb = __float2bfloat16(lo);
    wl[i] = *reinterpret_cast<unsigned short*>(&lb);
}

// ---------------- fused transpose (B,C,N) -> (B,N,C) for src1|src2 ----------------
__global__ void transpose_kernel(const float* __restrict__ src1, const float* __restrict__ src2,
                                 float* __restrict__ out) {
    __shared__ float t[32][33];
    int z = blockIdx.z;
    const float* in = (z < 4) ? src1 : src2;
    int b = z & 3;
    float* dst = out + (size_t)(z < 4 ? 0 : MTOK * CDIM) + (size_t)b * NPTS * CDIM;
    const float* sp = in + (size_t)b * CDIM * NPTS;
    int n0 = blockIdx.x * 32, c0 = blockIdx.y * 32;
    int tx = threadIdx.x, ty = threadIdx.y;
#pragma unroll
    for (int i = 0; i < 4; i++)
        t[ty + 8 * i][tx] = sp[(size_t)(c0 + ty + 8 * i) * NPTS + n0 + tx];
    __syncthreads();
#pragma unroll
    for (int i = 0; i < 4; i++)
        dst[(size_t)(n0 + ty + 8 * i) * CDIM + c0 + tx] = t[tx][ty + 8 * i];
}

// ---------------- bf16x3 tensor-core GEMM ----------------
// out[m,n] = epi( sum_k A[m,k]*W[n,k] + bias[n] ), W pre-split into bf16 hi/lo.
// CTA tile 64x64x16, 128 threads, 4 warps; warp tile 16(m) x 64(n); mma.m16n8k16.bf16, 3 terms.
// MODE 0: plain   MODE 1: gelu   MODE 2: + res[m,n], store transposed (b,c,n)
#define SA  20   // A smem row stride (floats)
#define SBW 12   // B smem row stride (words; row = 24 bf16, 16 used)

template <int MODE>
__global__ void __launch_bounds__(128) mma_gemm(
        const float* __restrict__ A,
        const unsigned short* __restrict__ Wh, const unsigned short* __restrict__ Wl,
        const float* __restrict__ bias, const float* __restrict__ res,
        float* __restrict__ out, int M, int N, int K) {
    __shared__ float    As[2][64 * SA];
    __shared__ unsigned Bh[2][64 * SBW];
    __shared__ unsigned Bl[2][64 * SBW];
    const int tid = threadIdx.x;
    const int lane = tid & 31, warp = tid >> 5;
    const int g = lane >> 2, tig = lane & 3;
    const int m0 = blockIdx.y * 64, n0 = blockIdx.x * 64;

    const int lrow = tid >> 1, lh = tid & 1;     // 64 rows x 2 halves
    const float* Ag = A + (size_t)(m0 + lrow) * K + lh * 8;
    const unsigned short* Whg = Wh + (size_t)(n0 + lrow) * K + lh * 8;
    const unsigned short* Wlg = Wl + (size_t)(n0 + lrow) * K + lh * 8;
    const unsigned sA  = (unsigned)__cvta_generic_to_shared(&As[0][0]) + (unsigned)(lrow * SA + lh * 8) * 4;
    const unsigned sBh = (unsigned)__cvta_generic_to_shared(&Bh[0][0]) + (unsigned)(lrow * 48 + lh * 16);
    const unsigned sBl = (unsigned)__cvta_generic_to_shared(&Bl[0][0]) + (unsigned)(lrow * 48 + lh * 16);
    const unsigned ABUF = 64 * SA * 4, BBUF = 64 * SBW * 4;

    float c[8][4];
#pragma unroll
    for (int i = 0; i < 8; i++)
#pragma unroll
        for (int j = 0; j < 4; j++) c[i][j] = 0.0f;

    const int nIter = K / 16;
    {   // prefetch tile 0
        CP_ASYNC16(sA, Ag);
        CP_ASYNC16(sA + 16, Ag + 4);
        CP_ASYNC16(sBh, Whg);
        CP_ASYNC16(sBl, Wlg);
        asm volatile("cp.async.commit_group;");
    }

    const int arow = warp * 16 + g;
    for (int kt = 0; kt < nIter; kt++) {
        asm volatile("cp.async.wait_group 0;");
        __syncthreads();
        const int buf = kt & 1;
        if (kt + 1 < nIter) {
            const int k1 = (kt + 1) * 16;
            const unsigned db = (buf ^ 1);
            CP_ASYNC16(sA + db * ABUF, Ag + k1);
            CP_ASYNC16(sA + db * ABUF + 16, Ag + k1 + 4);
            CP_ASYNC16(sBh + db * BBUF, Whg + k1);
            CP_ASYNC16(sBl + db * BBUF, Wlg + k1);
            asm volatile("cp.async.commit_group;");
        }
        const float*    as = &As[buf][0];
        const unsigned* bh = &Bh[buf][0];
        const unsigned* bl = &Bl[buf][0];

        unsigned AH[4], AL[4];
#pragma unroll
        for (int p = 0; p < 2; p++)
#pragma unroll
            for (int r = 0; r < 2; r++) {
                const float* ap = as + (arow + r * 8) * SA + p * 8 + 2 * tig;
                float2 xv = *reinterpret_cast<const float2*>(ap);
                split_pair(xv.x, xv.y, AH[p * 2 + r], AL[p * 2 + r]);
            }
#pragma unroll
        for (int nt = 0; nt < 8; nt++) {
            const int bn = nt * 8 + g;
            unsigned bh0 = bh[bn * SBW + tig],     bh1 = bh[bn * SBW + 4 + tig];
            unsigned bl0 = bl[bn * SBW + tig],     bl1 = bl[bn * SBW + 4 + tig];
            float* cc = c[nt];
#define MMA_BF16(A0,A1,A2,A3,B0,B1) \
    asm volatile("mma.sync.aligned.m16n8k16.row.col.f32.bf16.bf16.f32 " \
        "{%0,%1,%2,%3}, {%4,%5,%6,%7}, {%8,%9}, {%0,%1,%2,%3};" \
        : "+f"(cc[0]), "+f"(cc[1]), "+f"(cc[2]), "+f"(cc[3]) \
        : "r"(A0), "r"(A1), "r"(A2), "r"(A3), "r"(B0), "r"(B1))
            MMA_BF16(AH[0], AH[1], AH[2], AH[3], bl0, bl1);
            MMA_BF16(AL[0], AL[1], AL[2], AL[3], bh0, bh1);
            MMA_BF16(AH[0], AH[1], AH[2], AH[3], bh0, bh1);
#undef MMA_BF16
        }
        __syncthreads();
    }

    // epilogue
#pragma unroll
    for (int nt = 0; nt < 8; nt++) {
        int col = n0 + nt * 8 + tig * 2;
        float b0 = bias[col], b1 = bias[col + 1];
#pragma unroll
        for (int half = 0; half < 2; half++) {
            int m = m0 + warp * 16 + g + half * 8;
            float v0 = c[nt][half * 2 + 0] + b0;
            float v1 = c[nt][half * 2 + 1] + b1;
            if (MODE == 1) { v0 = gelu_exact(v0); v1 = gelu_exact(v1); }
            if (MODE == 2) {
                v0 += res[(size_t)m * CDIM + col];
                v1 += res[(size_t)m * CDIM + col + 1];
                int b = m >> 11, nn = m & (NPTS - 1);
                out[((size_t)b * CDIM + col) * NPTS + nn]     = v0;
                out[((size_t)b * CDIM + col + 1) * NPTS + nn] = v1;
            } else {
                *reinterpret_cast<float2*>(out + (size_t)m * N + col) = make_float2(v0, v1);
            }
        }
    }
}

// ---------------- LayerNorm: warp per row (256 cols), optional residual ----------------
__global__ void ln2_kernel(const float* __restrict__ x, const float* __restrict__ res,
                           const float* __restrict__ g, const float* __restrict__ be,
                           float* __restrict__ out) {
    int warp = threadIdx.x >> 5, lane = threadIdx.x & 31;
    size_t row = (size_t)blockIdx.x * 8 + warp;
    const float* xr = x + row * CDIM;
    float v[8], s = 0.0f, s2 = 0.0f;
#pragma unroll
    for (int i = 0; i < 8; i++) {
        v[i] = xr[i * 32 + lane];
        if (res) v[i] += res[row * CDIM + i * 32 + lane];
        s += v[i]; s2 += v[i] * v[i];
    }
#pragma unroll
    for (int o = 16; o > 0; o >>= 1) {
        s  += __shfl_xor_sync(0xffffffffu, s, o);
        s2 += __shfl_xor_sync(0xffffffffu, s2, o);
    }
    float mean = s * (1.0f / 256.0f);
    float var  = s2 * (1.0f / 256.0f) - mean * mean;
    float rstd = rsqrtf(var + 1e-5f);
#pragma unroll
    for (int i = 0; i < 8; i++)
        out[row * CDIM + i * 32 + lane] = (v[i] - mean) * rstd * g[i * 32 + lane] + be[i * 32 + lane];
}

// ---------------- KNN top-16 + rel-pos bias MLP ----------------
__global__ void knn_kernel(const float* __restrict__ pos,
                           const float* __restrict__ Wr1, const float* __restrict__ br1,
                           const float* __restrict__ Wr2, const float* __restrict__ br2,
                           int* __restrict__ idx_out, float* __restrict__ bias_out) {
    __shared__ float dist[NPTS];
    __shared__ unsigned long long rbuf[256];
    __shared__ int selj[NKNN];
    int bq = blockIdx.x;
    int b = bq >> 11, i = bq & (NPTS - 1);
    int t = threadIdx.x;
    const float* P = pos + (size_t)b * 3 * NPTS;
    float xi = P[i], yi = P[NPTS + i], zi = P[2 * NPTS + i];
    float sqi = xi * xi + yi * yi + zi * zi;
    for (int j = t; j < NPTS; j += 256) {
        float xj = P[j], yj = P[NPTS + j], zj = P[2 * NPTS + j];
        float sqj = xj * xj + yj * yj + zj * zj;
        float dot = xi * xj + yi * yj + zi * zj;
        dist[j] = sqi + sqj - 2.0f * dot;
    }
    __syncthreads();
    for (int s = 0; s < NKNN; s++) {
        unsigned long long best = ~0ull;
        for (int j = t; j < NPTS; j += 256) {
            unsigned int db = __float_as_uint(dist[j]);
            db = (db & 0x80000000u) ? ~db : (db | 0x80000000u);
            unsigned long long key = ((unsigned long long)db << 32) | (unsigned int)j;
            if (key < best) best = key;
        }
        rbuf[t] = best; __syncthreads();
        for (int o = 128; o > 0; o >>= 1) {
            if (t < o && rbuf[t + o] < rbuf[t]) rbuf[t] = rbuf[t + o];
            __syncthreads();
        }
        if (t == 0) {
            int j = (int)(rbuf[0] & 0xffffffffull);
            selj[s] = j;
            dist[j] = __int_as_float(0x7f800000);
        }
        __syncthreads();
    }
    if (t < NKNN) {
        int j = selj[t];
        float rx = xi - P[j], ry = yi - P[NPTS + j], rz = zi - P[2 * NPTS + j];
        float acc = 0.0f;
#pragma unroll 8
        for (int o = 0; o < 64; o++) {
            float hp = Wr1[o * 3] * rx + Wr1[o * 3 + 1] * ry + Wr1[o * 3 + 2] * rz + br1[o];
            acc += Wr2[o] * gelu_exact(hp);
        }
        idx_out[(size_t)bq * NKNN + t] = j;
        bias_out[(size_t)bq * NKNN + t] = acc + br2[0];
    }
}

// ---------------- sparse attention (kv packed: row = [k(256) | v(256)]) ----------------
__global__ void attn_kernel(const float* __restrict__ q, const float* __restrict__ kv,
                            const int* __restrict__ idx, const float* __restrict__ bias,
                            float* __restrict__ out) {
    __shared__ int   sj[NKNN];
    __shared__ float sb[NKNN];
    __shared__ float sc[NHEAD][NKNN];
    int m = blockIdx.x;
    int b = m >> 11;
    int warp = threadIdx.x >> 5, lane = threadIdx.x & 31;
    if (threadIdx.x < NKNN) {
        sj[threadIdx.x] = idx[(size_t)m * NKNN + threadIdx.x];
        sb[threadIdx.x] = bias[(size_t)m * NKNN + threadIdx.x];
    }
    __syncthreads();
    int hoff = warp * 64;
    float q0 = q[(size_t)m * CDIM + hoff + lane];
    float q1 = q[(size_t)m * CDIM + hoff + 32 + lane];
    for (int kk = 0; kk < NKNN; kk++) {
        int j = sj[kk];
        size_t base = ((size_t)b * NPTS + j) * 512 + hoff;
        float d = q0 * kv[base + lane] + q1 * kv[base + 32 + lane];
#pragma unroll
        for (int o = 16; o > 0; o >>= 1) d += __shfl_xor_sync(0xffffffffu, d, o);
        if (lane == 0) sc[warp][kk] = d * 0.125f + sb[kk];
    }
    __syncwarp();
    float mx = -3.4e38f;
#pragma unroll
    for (int kk = 0; kk < NKNN; kk++) mx = fmaxf(mx, sc[warp][kk]);
    float w[NKNN]; float sum = 0.0f;
#pragma unroll
    for (int kk = 0; kk < NKNN; kk++) { w[kk] = expf(sc[warp][kk] - mx); sum += w[kk]; }
    float inv = 1.0f / sum;
    float o0 = 0.0f, o1 = 0.0f;
    for (int kk = 0; kk < NKNN; kk++) {
        int j = sj[kk];
        size_t base = ((size_t)b * NPTS + j) * 512 + 256 + hoff;
        float ww = w[kk] * inv;
        o0 += ww * kv[base + lane];
        o1 += ww * kv[base + 32 + lane];
    }
    out[(size_t)m * CDIM + hoff + lane]      = o0;
    out[(size_t)m * CDIM + hoff + 32 + lane] = o1;
}

// ---------------- driver ----------------
extern "C" void kernel_launch(void* const* d_in, const int* in_sizes, int n_in,
                              void* d_out, int out_size) {
    const float* src1 = (const float*)d_in[0];
    const float* src2 = (const float*)d_in[1];
    const float* pos  = (const float*)d_in[2];
    const float* Wp   = (const float*)d_in[3];
    const float* bp   = (const float*)d_in[4];
    const float* Wr1  = (const float*)d_in[5];
    const float* br1  = (const float*)d_in[6];
    const float* Wr2  = (const float*)d_in[7];
    const float* br2  = (const float*)d_in[8];
    const float* Wqkv = (const float*)d_in[9];
    const float* bqkv = (const float*)d_in[10];
    const float* Wo   = (const float*)d_in[11];
    const float* bo   = (const float*)d_in[12];
    const float* g13  = (const float*)d_in[13];
    const float* b13  = (const float*)d_in[14];
    const float* g12  = (const float*)d_in[15];
    const float* b12  = (const float*)d_in[16];
    const float* W1   = (const float*)d_in[17];
    const float* b1   = (const float*)d_in[18];
    const float* W2   = (const float*)d_in[19];
    const float* b2   = (const float*)d_in[20];
    float* out = (float*)d_out;

    float *t, *x, *qb, *kvb, *ao, *tp, *y, *h, *bv;
    unsigned short *wh, *wl;
    int* idxb;
    cudaGetSymbolAddress((void**)&t,  g_t);
    cudaGetSymbolAddress((void**)&x,  g_x);
    cudaGetSymbolAddress((void**)&qb, g_q);
    cudaGetSymbolAddress((void**)&kvb, g_kv);
    cudaGetSymbolAddress((void**)&ao, g_ao);
    cudaGetSymbolAddress((void**)&tp, g_tp);
    cudaGetSymbolAddress((void**)&y,  g_y);
    cudaGetSymbolAddress((void**)&h,  g_h);
    cudaGetSymbolAddress((void**)&wh, g_wh);
    cudaGetSymbolAddress((void**)&wl, g_wl);
    cudaGetSymbolAddress((void**)&bv, g_bv);
    cudaGetSymbolAddress((void**)&idxb, g_idx);

    // weight split prep
    split_weights<<<W_TOT / 256, 256>>>(Wp, Wqkv, Wo, W1, W2, wh, wl);

    // transpose src1|src2 -> g_t (B,N,C) x2
    dim3 gT(NPTS / 32, CDIM / 32, 8), bT(32, 8);
    transpose_kernel<<<gT, bT>>>(src1, src2, t);

    // input proj, both streams in one GEMM: M = 16384
    mma_gemm<0><<<dim3(CDIM / 64, 2 * MTOK / 64), 128>>>(t, wh + W_P, wl + W_P, bp, nullptr, x, 2 * MTOK, CDIM, CDIM);

    // norm13 over both halves
    ln2_kernel<<<2 * MTOK / 8, 256>>>(x, nullptr, g13, b13, x);

    knn_kernel<<<MTOK, 256>>>(pos, Wr1, br1, Wr2, br2, idxb, bv);

    // Q from x1; K|V (N=512) from x2
    mma_gemm<0><<<dim3(CDIM / 64, MTOK / 64), 128>>>(x, wh + W_QKV, wl + W_QKV, bqkv, nullptr, qb, MTOK, CDIM, CDIM);
    mma_gemm<0><<<dim3(512 / 64, MTOK / 64), 128>>>(x + (size_t)MTOK * CDIM,
                                                    wh + W_QKV + CDIM * CDIM, wl + W_QKV + CDIM * CDIM,
                                                    bqkv + CDIM, nullptr, kvb, MTOK, 512, CDIM);

    attn_kernel<<<MTOK, 128>>>(qb, kvb, idxb, bv, ao);

    mma_gemm<0><<<dim3(CDIM / 64, MTOK / 64), 128>>>(ao, wh + W_O, wl + W_O, bo, nullptr, tp, MTOK, CDIM, CDIM);

    ln2_kernel<<<MTOK / 8, 256>>>(x, tp, g12, b12, y);

    mma_gemm<1><<<dim3(DFFN / 64, MTOK / 64), 128>>>(y, wh + W_1, wl + W_1, b1, nullptr, h, MTOK, DFFN, CDIM);
    mma_gemm<2><<<dim3(CDIM / 64, MTOK / 64), 128>>>(h, wh + W_2, wl + W_2, b2, y, out, MTOK, CDIM, DFFN);
}

// round 8
// speedup vs baseline: 2.0055x; 1.2232x over previous
#include <cuda_runtime.h>
#include <cuda_bf16.h>
#include <math.h>

#define NB    4
#define NPTS  2048
#define CDIM  256
#define DFFN  1024
#define NHEAD 4
#define NKNN  16
#define MTOK  (NB*NPTS)   // 8192

// weight-split segment offsets (elements)
#define W_P    0
#define W_QKV  65536
#define W_O    262144
#define W_1    327680
#define W_2    589824
#define W_TOT  851968

// ---------------- scratch ----------------
__device__ __align__(16) float g_t [2*MTOK*CDIM];
__device__ __align__(16) float g_x [2*MTOK*CDIM];
__device__ __align__(16) float g_q [MTOK*CDIM];
__device__ __align__(16) float g_kv[MTOK*512];
__device__ __align__(16) float g_ao[MTOK*CDIM];
__device__ __align__(16) float g_tp[MTOK*CDIM];
__device__ __align__(16) float g_y [MTOK*CDIM];
__device__ __align__(16) float g_h [MTOK*DFFN];
__device__ __align__(16) unsigned short g_wh[W_TOT];
__device__ __align__(16) unsigned short g_wl[W_TOT];
__device__ __align__(16) int   g_idx[MTOK*NKNN];
__device__ __align__(16) float g_bv [MTOK*NKNN];

__device__ __forceinline__ float gelu_exact(float x) {
    return 0.5f * x * (1.0f + erff(x * 0.70710678118654752440f));
}

#define CP_ASYNC16(smem_u32, gptr) \
    asm volatile("cp.async.cg.shared.global [%0], [%1], 16;" :: "r"(smem_u32), "l"(gptr))

// split a float pair (x0 = even-k, x1 = odd-k) into packed bf16 hi and lo
__device__ __forceinline__ void split_pair(float x0, float x1, unsigned& hi, unsigned& lo) {
    unsigned r0 = __float_as_uint(x0), r1 = __float_as_uint(x1);
    asm("prmt.b32 %0, %1, %2, 0x7632;" : "=r"(hi) : "r"(r0), "r"(r1));
    float l0 = x0 - __uint_as_float(r0 & 0xffff0000u);
    float l1 = x1 - __uint_as_float(r1 & 0xffff0000u);
    asm("cvt.rn.bf16x2.f32 %0, %1, %2;" : "=r"(lo) : "f"(l1), "f"(l0));
}

// ---------------- weight split prep ----------------
__global__ void split_weights(const float* __restrict__ Wp, const float* __restrict__ Wqkv,
                              const float* __restrict__ Wo, const float* __restrict__ W1,
                              const float* __restrict__ W2,
                              unsigned short* __restrict__ wh, unsigned short* __restrict__ wl) {
    int i = blockIdx.x * 256 + threadIdx.x;
    if (i >= W_TOT) return;
    const float* src; int off;
    if      (i < W_QKV) { src = Wp;   off = i; }
    else if (i < W_O)   { src = Wqkv; off = i - W_QKV; }
    else if (i < W_1)   { src = Wo;   off = i - W_O; }
    else if (i < W_2)   { src = W1;   off = i - W_1; }
    else                { src = W2;   off = i - W_2; }
    float x = src[off];
    unsigned r = __float_as_uint(x);
    wh[i] = (unsigned short)(r >> 16);
    float lo = x - __uint_as_float(r & 0xffff0000u);
    __nv_bfloat16 lb = __float2bfloat16(lo);
    wl[i] = *reinterpret_cast<unsigned short*>(&lb);
}

// ---------------- fused transpose (B,C,N) -> (B,N,C) for src1|src2 ----------------
__global__ void transpose_kernel(const float* __restrict__ src1, const float* __restrict__ src2,
                                 float* __restrict__ out) {
    __shared__ float t[32][33];
    int z = blockIdx.z;
    const float* in = (z < 4) ? src1 : src2;
    int b = z & 3;
    float* dst = out + (size_t)(z < 4 ? 0 : MTOK * CDIM) + (size_t)b * NPTS * CDIM;
    const float* sp = in + (size_t)b * CDIM * NPTS;
    int n0 = blockIdx.x * 32, c0 = blockIdx.y * 32;
    int tx = threadIdx.x, ty = threadIdx.y;
#pragma unroll
    for (int i = 0; i < 4; i++)
        t[ty + 8 * i][tx] = sp[(size_t)(c0 + ty + 8 * i) * NPTS + n0 + tx];
    __syncthreads();
#pragma unroll
    for (int i = 0; i < 4; i++)
        dst[(size_t)(n0 + ty + 8 * i) * CDIM + c0 + tx] = t[tx][ty + 8 * i];
}

// ---------------- bf16x3 tensor-core GEMM ----------------
#define SA  20
#define SBW 12

template <int MODE>
__global__ void __launch_bounds__(128) mma_gemm(
        const float* __restrict__ A,
        const unsigned short* __restrict__ Wh, const unsigned short* __restrict__ Wl,
        const float* __restrict__ bias, const float* __restrict__ res,
        float* __restrict__ out, int M, int N, int K) {
    __shared__ float    As[2][64 * SA];
    __shared__ unsigned Bh[2][64 * SBW];
    __shared__ unsigned Bl[2][64 * SBW];
    const int tid = threadIdx.x;
    const int lane = tid & 31, warp = tid >> 5;
    const int g = lane >> 2, tig = lane & 3;
    const int m0 = blockIdx.y * 64, n0 = blockIdx.x * 64;

    const int lrow = tid >> 1, lh = tid & 1;
    const float* Ag = A + (size_t)(m0 + lrow) * K + lh * 8;
    const unsigned short* Whg = Wh + (size_t)(n0 + lrow) * K + lh * 8;
    const unsigned short* Wlg = Wl + (size_t)(n0 + lrow) * K + lh * 8;
    const unsigned sA  = (unsigned)__cvta_generic_to_shared(&As[0][0]) + (unsigned)(lrow * SA + lh * 8) * 4;
    const unsigned sBh = (unsigned)__cvta_generic_to_shared(&Bh[0][0]) + (unsigned)(lrow * 48 + lh * 16);
    const unsigned sBl = (unsigned)__cvta_generic_to_shared(&Bl[0][0]) + (unsigned)(lrow * 48 + lh * 16);
    const unsigned ABUF = 64 * SA * 4, BBUF = 64 * SBW * 4;

    float c[8][4];
#pragma unroll
    for (int i = 0; i < 8; i++)
#pragma unroll
        for (int j = 0; j < 4; j++) c[i][j] = 0.0f;

    const int nIter = K / 16;
    {
        CP_ASYNC16(sA, Ag);
        CP_ASYNC16(sA + 16, Ag + 4);
        CP_ASYNC16(sBh, Whg);
        CP_ASYNC16(sBl, Wlg);
        asm volatile("cp.async.commit_group;");
    }

    const int arow = warp * 16 + g;
    for (int kt = 0; kt < nIter; kt++) {
        asm volatile("cp.async.wait_group 0;");
        __syncthreads();
        const int buf = kt & 1;
        if (kt + 1 < nIter) {
            const int k1 = (kt + 1) * 16;
            const unsigned db = (buf ^ 1);
            CP_ASYNC16(sA + db * ABUF, Ag + k1);
            CP_ASYNC16(sA + db * ABUF + 16, Ag + k1 + 4);
            CP_ASYNC16(sBh + db * BBUF, Whg + k1);
            CP_ASYNC16(sBl + db * BBUF, Wlg + k1);
            asm volatile("cp.async.commit_group;");
        }
        const float*    as = &As[buf][0];
        const unsigned* bh = &Bh[buf][0];
        const unsigned* bl = &Bl[buf][0];

        unsigned AH[4], AL[4];
#pragma unroll
        for (int p = 0; p < 2; p++)
#pragma unroll
            for (int r = 0; r < 2; r++) {
                const float* ap = as + (arow + r * 8) * SA + p * 8 + 2 * tig;
                float2 xv = *reinterpret_cast<const float2*>(ap);
                split_pair(xv.x, xv.y, AH[p * 2 + r], AL[p * 2 + r]);
            }
#pragma unroll
        for (int nt = 0; nt < 8; nt++) {
            const int bn = nt * 8 + g;
            unsigned bh0 = bh[bn * SBW + tig],     bh1 = bh[bn * SBW + 4 + tig];
            unsigned bl0 = bl[bn * SBW + tig],     bl1 = bl[bn * SBW + 4 + tig];
            float* cc = c[nt];
#define MMA_BF16(A0,A1,A2,A3,B0,B1) \
    asm volatile("mma.sync.aligned.m16n8k16.row.col.f32.bf16.bf16.f32 " \
        "{%0,%1,%2,%3}, {%4,%5,%6,%7}, {%8,%9}, {%0,%1,%2,%3};" \
        : "+f"(cc[0]), "+f"(cc[1]), "+f"(cc[2]), "+f"(cc[3]) \
        : "r"(A0), "r"(A1), "r"(A2), "r"(A3), "r"(B0), "r"(B1))
            MMA_BF16(AH[0], AH[1], AH[2], AH[3], bl0, bl1);
            MMA_BF16(AL[0], AL[1], AL[2], AL[3], bh0, bh1);
            MMA_BF16(AH[0], AH[1], AH[2], AH[3], bh0, bh1);
#undef MMA_BF16
        }
        __syncthreads();
    }

#pragma unroll
    for (int nt = 0; nt < 8; nt++) {
        int col = n0 + nt * 8 + tig * 2;
        float b0 = bias[col], b1 = bias[col + 1];
#pragma unroll
        for (int half = 0; half < 2; half++) {
            int m = m0 + warp * 16 + g + half * 8;
            float v0 = c[nt][half * 2 + 0] + b0;
            float v1 = c[nt][half * 2 + 1] + b1;
            if (MODE == 1) { v0 = gelu_exact(v0); v1 = gelu_exact(v1); }
            if (MODE == 2) {
                v0 += res[(size_t)m * CDIM + col];
                v1 += res[(size_t)m * CDIM + col + 1];
                int b = m >> 11, nn = m & (NPTS - 1);
                out[((size_t)b * CDIM + col) * NPTS + nn]     = v0;
                out[((size_t)b * CDIM + col + 1) * NPTS + nn] = v1;
            } else {
                *reinterpret_cast<float2*>(out + (size_t)m * N + col) = make_float2(v0, v1);
            }
        }
    }
}

// ---------------- LayerNorm: warp per row (256 cols), optional residual ----------------
__global__ void ln2_kernel(const float* __restrict__ x, const float* __restrict__ res,
                           const float* __restrict__ g, const float* __restrict__ be,
                           float* __restrict__ out) {
    int warp = threadIdx.x >> 5, lane = threadIdx.x & 31;
    size_t row = (size_t)blockIdx.x * 8 + warp;
    const float* xr = x + row * CDIM;
    float v[8], s = 0.0f, s2 = 0.0f;
#pragma unroll
    for (int i = 0; i < 8; i++) {
        v[i] = xr[i * 32 + lane];
        if (res) v[i] += res[row * CDIM + i * 32 + lane];
        s += v[i]; s2 += v[i] * v[i];
    }
#pragma unroll
    for (int o = 16; o > 0; o >>= 1) {
        s  += __shfl_xor_sync(0xffffffffu, s, o);
        s2 += __shfl_xor_sync(0xffffffffu, s2, o);
    }
    float mean = s * (1.0f / 256.0f);
    float var  = s2 * (1.0f / 256.0f) - mean * mean;
    float rstd = rsqrtf(var + 1e-5f);
#pragma unroll
    for (int i = 0; i < 8; i++)
        out[row * CDIM + i * 32 + lane] = (v[i] - mean) * rstd * g[i * 32 + lane] + be[i * 32 + lane];
}

// ---------------- KNN top-16 via exact 4-round radix select + rel-pos bias MLP ----------------
// one block (256 thr) per query. keys = mono32(dist)<<32 | j  (strict total order).
#define TIECAP 128
__global__ void knn_kernel(const float* __restrict__ pos,
                           const float* __restrict__ Wr1, const float* __restrict__ br1,
                           const float* __restrict__ Wr2, const float* __restrict__ br2,
                           int* __restrict__ idx_out, float* __restrict__ bias_out) {
    __shared__ unsigned long long keys[NPTS];   // 16KB
    __shared__ int hist[256];
    __shared__ int sel[NKNN];
    __shared__ int tiebuf[TIECAP];
    __shared__ int cnts[2];                      // [0]=below count, [1]=tie count
    __shared__ unsigned sh_prefix;
    __shared__ int sh_krem;
    int bq = blockIdx.x;
    int b = bq >> 11, i = bq & (NPTS - 1);
    int t = threadIdx.x;
    const float* P = pos + (size_t)b * 3 * NPTS;
    float xi = P[i], yi = P[NPTS + i], zi = P[2 * NPTS + i];
    float sqi = xi * xi + yi * yi + zi * zi;
    for (int j = t; j < NPTS; j += 256) {
        float xj = P[j], yj = P[NPTS + j], zj = P[2 * NPTS + j];
        float sqj = xj * xj + yj * yj + zj * zj;
        float dot = xi * xj + yi * yj + zi * zj;
        float dist = sqi + sqj - 2.0f * dot;
        unsigned db = __float_as_uint(dist);
        db = (db & 0x80000000u) ? ~db : (db | 0x80000000u);
        keys[j] = ((unsigned long long)db << 32) | (unsigned)j;
    }
    if (t == 0) { cnts[0] = 0; cnts[1] = 0; }

    unsigned prefix = 0;
    int krem = NKNN;
#pragma unroll
    for (int r = 0; r < 4; r++) {
        const int shift = 24 - 8 * r;
        hist[t] = 0;
        __syncthreads();
        for (int j = t; j < NPTS; j += 256) {
            unsigned d32 = (unsigned)(keys[j] >> 32);
            bool match = (r == 0) || ((d32 >> (shift + 8)) == (prefix >> (shift + 8)));
            if (match) {
                int digit = (d32 >> shift) & 0xFF;
                unsigned mask = __match_any_sync(__activemask(), digit);
                int leader = __ffs(mask) - 1;
                if ((int)(t & 31) == leader) atomicAdd(&hist[digit], __popc(mask));
            }
        }
        __syncthreads();
        if (t < 32) {
            int loc[8], s = 0;
#pragma unroll
            for (int u = 0; u < 8; u++) { loc[u] = s; s += hist[t * 8 + u]; }
            int run = s;
#pragma unroll
            for (int o = 1; o < 32; o <<= 1) {
                int v = __shfl_up_sync(0xffffffffu, run, o);
                if (t >= o) run += v;
            }
            int excl = run - s;
#pragma unroll
            for (int u = 0; u < 8; u++) {
                int below = excl + loc[u];
                int c = hist[t * 8 + u];
                if (below < krem && krem <= below + c) {
                    sh_prefix = prefix | ((unsigned)(t * 8 + u) << shift);
                    sh_krem = krem - below;
                }
            }
        }
        __syncthreads();
        prefix = sh_prefix;
        krem = sh_krem;
        __syncthreads();
    }

    // collect: strictly-below (exactly 16-krem of them) + ties (dist == pivot)
    for (int j = t; j < NPTS; j += 256) {
        unsigned d32 = (unsigned)(keys[j] >> 32);
        if (d32 < prefix) {
            int p = atomicAdd(&cnts[0], 1);
            sel[p] = j;
        } else if (d32 == prefix) {
            int p = atomicAdd(&cnts[1], 1);
            if (p < TIECAP) tiebuf[p] = j;
        }
    }
    __syncthreads();
    if (t == 0) {
        int na = cnts[0];
        int nt = cnts[1] < TIECAP ? cnts[1] : TIECAP;
        // sort below-set ascending (determinism)
        for (int a = 1; a < na; a++) {
            int v = sel[a], p = a - 1;
            while (p >= 0 && sel[p] > v) { sel[p + 1] = sel[p]; p--; }
            sel[p + 1] = v;
        }
        // take krem smallest-index ties (stable top-k tie-break)
        for (int s = 0; s < NKNN - na; s++) {
            int bestv = 1 << 30, bi = 0;
            for (int u = 0; u < nt; u++)
                if (tiebuf[u] < bestv) { bestv = tiebuf[u]; bi = u; }
            sel[na + s] = bestv;
            tiebuf[bi] = 1 << 30;
        }
    }
    __syncthreads();

    if (t < NKNN) {
        int j = sel[t];
        float rx = xi - P[j], ry = yi - P[NPTS + j], rz = zi - P[2 * NPTS + j];
        float acc = 0.0f;
#pragma unroll 8
        for (int o = 0; o < 64; o++) {
            float hp = Wr1[o * 3] * rx + Wr1[o * 3 + 1] * ry + Wr1[o * 3 + 2] * rz + br1[o];
            acc += Wr2[o] * gelu_exact(hp);
        }
        idx_out[(size_t)bq * NKNN + t] = j;
        bias_out[(size_t)bq * NKNN + t] = acc + br2[0];
    }
}

// ---------------- sparse attention (kv packed: row = [k(256) | v(256)]) ----------------
__global__ void attn_kernel(const float* __restrict__ q, const float* __restrict__ kv,
                            const int* __restrict__ idx, const float* __restrict__ bias,
                            float* __restrict__ out) {
    __shared__ int   sj[NKNN];
    __shared__ float sb[NKNN];
    int m = blockIdx.x;
    int b = m >> 11;
    int warp = threadIdx.x >> 5, lane = threadIdx.x & 31;
    if (threadIdx.x < NKNN) {
        sj[threadIdx.x] = idx[(size_t)m * NKNN + threadIdx.x];
        sb[threadIdx.x] = bias[(size_t)m * NKNN + threadIdx.x];
    }
    __syncthreads();
    int hoff = warp * 64;
    float q0 = q[(size_t)m * CDIM + hoff + lane];
    float q1 = q[(size_t)m * CDIM + hoff + 32 + lane];
    // batch the 32 independent k-loads, then reduce
    float k0[NKNN], k1[NKNN];
#pragma unroll
    for (int kk = 0; kk < NKNN; kk++) {
        size_t base = ((size_t)b * NPTS + sj[kk]) * 512 + hoff;
        k0[kk] = kv[base + lane];
        k1[kk] = kv[base + 32 + lane];
    }
    float sc[NKNN];
#pragma unroll
    for (int kk = 0; kk < NKNN; kk++) {
        float d = q0 * k0[kk] + q1 * k1[kk];
#pragma unroll
        for (int o = 16; o > 0; o >>= 1) d += __shfl_xor_sync(0xffffffffu, d, o);
        sc[kk] = d * 0.125f + sb[kk];
    }
    float mx = -3.4e38f;
#pragma unroll
    for (int kk = 0; kk < NKNN; kk++) mx = fmaxf(mx, sc[kk]);
    float sum = 0.0f;
#pragma unroll
    for (int kk = 0; kk < NKNN; kk++) { sc[kk] = expf(sc[kk] - mx); sum += sc[kk]; }
    float inv = 1.0f / sum;
    // batch v-loads (reuse k0/k1 registers)
#pragma unroll
    for (int kk = 0; kk < NKNN; kk++) {
        size_t base = ((size_t)b * NPTS + sj[kk]) * 512 + 256 + hoff;
        k0[kk] = kv[base + lane];
        k1[kk] = kv[base + 32 + lane];
    }
    float o0 = 0.0f, o1 = 0.0f;
#pragma unroll
    for (int kk = 0; kk < NKNN; kk++) {
        float ww = sc[kk] * inv;
        o0 += ww * k0[kk];
        o1 += ww * k1[kk];
    }
    out[(size_t)m * CDIM + hoff + lane]      = o0;
    out[(size_t)m * CDIM + hoff + 32 + lane] = o1;
}

// ---------------- driver ----------------
extern "C" void kernel_launch(void* const* d_in, const int* in_sizes, int n_in,
                              void* d_out, int out_size) {
    const float* src1 = (const float*)d_in[0];
    const float* src2 = (const float*)d_in[1];
    const float* pos  = (const float*)d_in[2];
    const float* Wp   = (const float*)d_in[3];
    const float* bp   = (const float*)d_in[4];
    const float* Wr1  = (const float*)d_in[5];
    const float* br1  = (const float*)d_in[6];
    const float* Wr2  = (const float*)d_in[7];
    const float* br2  = (const float*)d_in[8];
    const float* Wqkv = (const float*)d_in[9];
    const float* bqkv = (const float*)d_in[10];
    const float* Wo   = (const float*)d_in[11];
    const float* bo   = (const float*)d_in[12];
    const float* g13  = (const float*)d_in[13];
    const float* b13  = (const float*)d_in[14];
    const float* g12  = (const float*)d_in[15];
    const float* b12  = (const float*)d_in[16];
    const float* W1   = (const float*)d_in[17];
    const float* b1   = (const float*)d_in[18];
    const float* W2   = (const float*)d_in[19];
    const float* b2   = (const float*)d_in[20];
    float* out = (float*)d_out;

    float *t, *x, *qb, *kvb, *ao, *tp, *y, *h, *bv;
    unsigned short *wh, *wl;
    int* idxb;
    cudaGetSymbolAddress((void**)&t,  g_t);
    cudaGetSymbolAddress((void**)&x,  g_x);
    cudaGetSymbolAddress((void**)&qb, g_q);
    cudaGetSymbolAddress((void**)&kvb, g_kv);
    cudaGetSymbolAddress((void**)&ao, g_ao);
    cudaGetSymbolAddress((void**)&tp, g_tp);
    cudaGetSymbolAddress((void**)&y,  g_y);
    cudaGetSymbolAddress((void**)&h,  g_h);
    cudaGetSymbolAddress((void**)&wh, g_wh);
    cudaGetSymbolAddress((void**)&wl, g_wl);
    cudaGetSymbolAddress((void**)&bv, g_bv);
    cudaGetSymbolAddress((void**)&idxb, g_idx);

    split_weights<<<W_TOT / 256, 256>>>(Wp, Wqkv, Wo, W1, W2, wh, wl);

    dim3 gT(NPTS / 32, CDIM / 32, 8), bT(32, 8);
    transpose_kernel<<<gT, bT>>>(src1, src2, t);

    mma_gemm<0><<<dim3(CDIM / 64, 2 * MTOK / 64), 128>>>(t, wh + W_P, wl + W_P, bp, nullptr, x, 2 * MTOK, CDIM, CDIM);

    ln2_kernel<<<2 * MTOK / 8, 256>>>(x, nullptr, g13, b13, x);

    knn_kernel<<<MTOK, 256>>>(pos, Wr1, br1, Wr2, br2, idxb, bv);

    mma_gemm<0><<<dim3(CDIM / 64, MTOK / 64), 128>>>(x, wh + W_QKV, wl + W_QKV, bqkv, nullptr, qb, MTOK, CDIM, CDIM);
    mma_gemm<0><<<dim3(512 / 64, MTOK / 64), 128>>>(x + (size_t)MTOK * CDIM,
                                                    wh + W_QKV + CDIM * CDIM, wl + W_QKV + CDIM * CDIM,
                                                    bqkv + CDIM, nullptr, kvb, MTOK, 512, CDIM);

    attn_kernel<<<MTOK, 128>>>(qb, kvb, idxb, bv, ao);

    mma_gemm<0><<<dim3(CDIM / 64, MTOK / 64), 128>>>(ao, wh + W_O, wl + W_O, bo, nullptr, tp, MTOK, CDIM, CDIM);

    ln2_kernel<<<MTOK / 8, 256>>>(x, tp, g12, b12, y);

    mma_gemm<1><<<dim3(DFFN / 64, MTOK / 64), 128>>>(y, wh + W_1, wl + W_1, b1, nullptr, h, MTOK, DFFN, CDIM);
    mma_gemm<2><<<dim3(CDIM / 64, MTOK / 64), 128>>>(h, wh + W_2, wl + W_2, b2, y, out, MTOK, CDIM, DFFN);
}